// round 1
// baseline (speedup 1.0000x reference)
#include <cuda_runtime.h>
#include <math.h>

#define NB 2
#define CIN 64
#define TF 16
#define HF 48
#define WF 48
#define tT 8
#define tH 24
#define tW 24
#define NN 4608             // tT*tH*tW
#define HWt 576             // tH*tW
#define NFULL 36864         // TF*HF*WF

// -------- scratch (device globals; no allocations) --------
__device__ float g_xr[2*NB*CIN*NN];       // [src][b][c][n]
__device__ float g_q  [NB*NN*16];
__device__ float g_k  [NB*NN*16];
__device__ float g_v  [NB*NN*32];
__device__ float g_qsa[NB*NN*16];
__device__ float g_ksa[NB*NN*16];
__device__ float g_vsa[NB*NN*32];
__device__ float g_out[2*NB*NN*32];       // [attn][b][n][c]
__device__ float g_comb[NB*64*NN];        // [b][c][n]
__device__ float g_stats[8];              // [attn][b][{mean,rstd}]

// ---------------- K1: trilinear downsample ----------------
__global__ void k_resize_down(const float* __restrict__ x, const float* __restrict__ xc) {
    int idx = blockIdx.x * blockDim.x + threadIdx.x;
    const int total = 2*NB*CIN*NN;
    if (idx >= total) return;
    int n = idx % NN;
    int rest = idx / NN;
    int c = rest % CIN; rest /= CIN;
    int b = rest % NB;
    int src = rest / NB;

    int ww = n % tW;
    int hh = (n / tW) % tH;
    int tt = n / HWt;

    float pt = (float)tt * ((float)(TF-1)/(float)(tT-1));
    int t0 = (int)floorf(pt); t0 = t0 < 0 ? 0 : (t0 > TF-1 ? TF-1 : t0);
    int t1 = t0+1 > TF-1 ? TF-1 : t0+1;
    float wt = pt - (float)t0;

    float ph = (float)hh * ((float)(HF-1)/(float)(tH-1));
    int h0 = (int)floorf(ph); h0 = h0 < 0 ? 0 : (h0 > HF-1 ? HF-1 : h0);
    int h1 = h0+1 > HF-1 ? HF-1 : h0+1;
    float wh = ph - (float)h0;

    float pw = (float)ww * ((float)(WF-1)/(float)(tW-1));
    int w0 = (int)floorf(pw); w0 = w0 < 0 ? 0 : (w0 > WF-1 ? WF-1 : w0);
    int w1 = w0+1 > WF-1 ? WF-1 : w0+1;
    float wwf = pw - (float)w0;

    const float* sp = src ? xc : x;
    const float* base = sp + (size_t)(b*CIN + c) * NFULL;

    float a00 = base[t0*HF*WF + h0*WF + w0];
    float a01 = base[t0*HF*WF + h0*WF + w1];
    float a10 = base[t0*HF*WF + h1*WF + w0];
    float a11 = base[t0*HF*WF + h1*WF + w1];
    float b00 = base[t1*HF*WF + h0*WF + w0];
    float b01 = base[t1*HF*WF + h0*WF + w1];
    float b10 = base[t1*HF*WF + h1*WF + w0];
    float b11 = base[t1*HF*WF + h1*WF + w1];

    float va0 = a00 + (a01 - a00)*wwf;
    float va1 = a10 + (a11 - a10)*wwf;
    float vb0 = b00 + (b01 - b00)*wwf;
    float vb1 = b10 + (b11 - b10)*wwf;
    float va = va0 + (va1 - va0)*wh;
    float vb = vb0 + (vb1 - vb0)*wh;
    g_xr[idx] = va + (vb - va)*wt;
}

// ---------------- K2: down-proj + all projections + RoPE ----------------
__global__ void k_proj(const float* __restrict__ wd,  const float* __restrict__ bd,
                       const float* __restrict__ wdc, const float* __restrict__ bdc,
                       const float* __restrict__ wq,  const float* __restrict__ bq,
                       const float* __restrict__ wk,  const float* __restrict__ bk,
                       const float* __restrict__ wv,  const float* __restrict__ bv,
                       const float* __restrict__ wqs, const float* __restrict__ bqs,
                       const float* __restrict__ wks, const float* __restrict__ bks,
                       const float* __restrict__ wvs, const float* __restrict__ bvs,
                       const float* __restrict__ offE, const float* __restrict__ offC) {
    __shared__ float s[8192 + 192];
    float* s_wd  = s;           // 2048
    float* s_wdc = s + 2048;    // 2048
    float* s_wq  = s + 4096;    // 512
    float* s_wk  = s + 4608;    // 512
    float* s_wqs = s + 5120;    // 512
    float* s_wks = s + 5632;    // 512
    float* s_wv  = s + 6144;    // 1024
    float* s_wvs = s + 7168;    // 1024
    float* s_b   = s + 8192;    // 192 biases

    int tid = threadIdx.x;
    for (int i = tid; i < 2048; i += 256) { s_wd[i] = wd[i]; s_wdc[i] = wdc[i]; }
    for (int i = tid; i < 512;  i += 256) { s_wq[i] = wq[i]; s_wk[i] = wk[i]; s_wqs[i] = wqs[i]; s_wks[i] = wks[i]; }
    for (int i = tid; i < 1024; i += 256) { s_wv[i] = wv[i]; s_wvs[i] = wvs[i]; }
    if (tid < 32) { s_b[tid] = bd[tid];  s_b[32+tid]  = bdc[tid];
                    s_b[128+tid] = bv[tid]; s_b[160+tid] = bvs[tid]; }
    if (tid < 16) { s_b[64+tid] = bq[tid];  s_b[80+tid]  = bk[tid];
                    s_b[96+tid] = bqs[tid]; s_b[112+tid] = bks[tid]; }
    __syncthreads();

    int gid = blockIdx.x * blockDim.x + tid;
    if (gid >= NB*NN) return;
    int b = gid / NN, n = gid % NN;

    float xd[32], xcd[32];
    #pragma unroll
    for (int o = 0; o < 32; o++) { xd[o] = s_b[o]; xcd[o] = s_b[32+o]; }

    const float* xrx = g_xr + ((size_t)(0*NB + b) * CIN) * NN + n;
    const float* xrc = g_xr + ((size_t)(1*NB + b) * CIN) * NN + n;
    for (int c = 0; c < 64; c++) {
        float vx = xrx[(size_t)c * NN];
        float vc = xrc[(size_t)c * NN];
        #pragma unroll
        for (int o = 0; o < 32; o++) {
            xd[o]  += s_wd [o*64 + c] * vx;
            xcd[o] += s_wdc[o*64 + c] * vc;
        }
    }

    // RoPE factors for this token's t
    int t = n / HWt;
    float se[8], ce[8], scf[8], ccf[8];
    #pragma unroll
    for (int i = 0; i < 8; i++) {
        float invf = powf(10000.0f, -(float)i / 8.0f);
        float f = (float)t * invf;
        float sv = sinf(f), cv = cosf(f);
        float oe = offE[i*500 + t];
        float oc = offC[i*500 + t];
        se[i]  = sv + oe; ce[i]  = cv + oe;
        scf[i] = sv + oc; ccf[i] = cv + oc;
    }

    float pre[16];
    // q = rope(wq @ xd, sin_e/cos_e)
    #pragma unroll
    for (int o = 0; o < 16; o++) {
        float a = s_b[64+o];
        #pragma unroll
        for (int c = 0; c < 32; c++) a += s_wq[o*32+c] * xd[c];
        pre[o] = a;
    }
    {
        float* qo = g_q + ((size_t)b*NN + n) * 16;
        #pragma unroll
        for (int i = 0; i < 8; i++) {
            qo[i]   = pre[i]*ce[i]   - pre[i+8]*se[i];
            qo[i+8] = pre[i+8]*ce[i] + pre[i]*se[i];
        }
    }
    // k = rope(wk @ xcd, sin_c/cos_c)
    #pragma unroll
    for (int o = 0; o < 16; o++) {
        float a = s_b[80+o];
        #pragma unroll
        for (int c = 0; c < 32; c++) a += s_wk[o*32+c] * xcd[c];
        pre[o] = a;
    }
    {
        float* ko = g_k + ((size_t)b*NN + n) * 16;
        #pragma unroll
        for (int i = 0; i < 8; i++) {
            ko[i]   = pre[i]*ccf[i]   - pre[i+8]*scf[i];
            ko[i+8] = pre[i+8]*ccf[i] + pre[i]*scf[i];
        }
    }
    // q_sa = rope(wqs @ xcd, sin_e/cos_e)
    #pragma unroll
    for (int o = 0; o < 16; o++) {
        float a = s_b[96+o];
        #pragma unroll
        for (int c = 0; c < 32; c++) a += s_wqs[o*32+c] * xcd[c];
        pre[o] = a;
    }
    {
        float* qo = g_qsa + ((size_t)b*NN + n) * 16;
        #pragma unroll
        for (int i = 0; i < 8; i++) {
            qo[i]   = pre[i]*ce[i]   - pre[i+8]*se[i];
            qo[i+8] = pre[i+8]*ce[i] + pre[i]*se[i];
        }
    }
    // k_sa = rope(wks @ xcd, sin_e/cos_e)
    #pragma unroll
    for (int o = 0; o < 16; o++) {
        float a = s_b[112+o];
        #pragma unroll
        for (int c = 0; c < 32; c++) a += s_wks[o*32+c] * xcd[c];
        pre[o] = a;
    }
    {
        float* ko = g_ksa + ((size_t)b*NN + n) * 16;
        #pragma unroll
        for (int i = 0; i < 8; i++) {
            ko[i]   = pre[i]*ce[i]   - pre[i+8]*se[i];
            ko[i+8] = pre[i+8]*ce[i] + pre[i]*se[i];
        }
    }
    // v = wv @ xcd ; v_sa = wvs @ xcd
    {
        float* vo  = g_v   + ((size_t)b*NN + n) * 32;
        float* vso = g_vsa + ((size_t)b*NN + n) * 32;
        #pragma unroll
        for (int o = 0; o < 32; o++) {
            float a = s_b[128+o], a2 = s_b[160+o];
            #pragma unroll
            for (int c = 0; c < 32; c++) {
                a  += s_wv [o*32+c] * xcd[c];
                a2 += s_wvs[o*32+c] * xcd[c];
            }
            vo[o] = a; vso[o] = a2;
        }
    }
}

// ---------------- K3: flash attention (1 query / thread) ----------------
#define QT 128
#define MT 128
__global__ void __launch_bounds__(QT) k_attn() {
    int a = blockIdx.z;
    int b = blockIdx.y;
    int n = blockIdx.x * QT + threadIdx.x;

    const float* qp = a ? g_qsa : g_q;
    const float* kp = a ? g_ksa : g_k;
    const float* vp = a ? g_vsa : g_v;
    float* op = g_out + (size_t)a * NB * NN * 32;

    __shared__ float ks[MT][16];
    __shared__ float vs[MT][32];

    float q[16];
    const float* qrow = qp + ((size_t)b*NN + n) * 16;
    #pragma unroll
    for (int i = 0; i < 16; i++) q[i] = qrow[i];

    float mval = -INFINITY, dsum = 0.f;
    float acc[32];
    #pragma unroll
    for (int c = 0; c < 32; c++) acc[c] = 0.f;

    for (int mt = 0; mt < NN; mt += MT) {
        __syncthreads();
        {
            const float4* krow = (const float4*)(kp + ((size_t)b*NN + mt + threadIdx.x) * 16);
            float4* kdst = (float4*)ks[threadIdx.x];
            #pragma unroll
            for (int i = 0; i < 4; i++) kdst[i] = krow[i];
            const float4* vrow = (const float4*)(vp + ((size_t)b*NN + mt + threadIdx.x) * 32);
            float4* vdst = (float4*)vs[threadIdx.x];
            #pragma unroll
            for (int i = 0; i < 8; i++) vdst[i] = vrow[i];
        }
        __syncthreads();

        for (int mm = 0; mm < MT; mm++) {
            float s0 = 0.f, s1 = 0.f, s2 = 0.f, s3 = 0.f;
            #pragma unroll
            for (int i = 0; i < 4; i++) {
                s0 += q[i]      * ks[mm][i];
                s1 += q[4 + i]  * ks[mm][4 + i];
                s2 += q[8 + i]  * ks[mm][8 + i];
                s3 += q[12 + i] * ks[mm][12 + i];
            }
            float sc = (s0 + s1 + s2 + s3) * 0.5f;
            if (sc > mval) {
                float corr = __expf(mval - sc);
                dsum *= corr;
                #pragma unroll
                for (int c = 0; c < 32; c++) acc[c] *= corr;
                mval = sc;
            }
            float p = __expf(sc - mval);
            dsum += p;
            #pragma unroll
            for (int c = 0; c < 32; c++) acc[c] += p * vs[mm][c];
        }
    }

    float inv = 1.0f / dsum;
    float* orow = op + ((size_t)b*NN + n) * 32;
    #pragma unroll
    for (int c = 0; c < 32; c++) orow[c] = acc[c] * inv;
}

// ---------------- K4: groupnorm statistics ----------------
__global__ void k_stats() {
    int a = blockIdx.x >> 1;
    int b = blockIdx.x & 1;
    const float* p = g_out + ((size_t)a*NB + b) * NN * 32;
    const int M = NN * 32;
    double s = 0.0, s2 = 0.0;
    for (int i = threadIdx.x; i < M; i += blockDim.x) {
        float v = p[i];
        s  += (double)v;
        s2 += (double)v * (double)v;
    }
    __shared__ double rs[256], rs2[256];
    rs[threadIdx.x] = s; rs2[threadIdx.x] = s2;
    __syncthreads();
    for (int st = 128; st > 0; st >>= 1) {
        if (threadIdx.x < st) {
            rs[threadIdx.x]  += rs[threadIdx.x + st];
            rs2[threadIdx.x] += rs2[threadIdx.x + st];
        }
        __syncthreads();
    }
    if (threadIdx.x == 0) {
        double mean = rs[0] / (double)M;
        double var  = rs2[0] / (double)M - mean * mean;
        g_stats[(a*2 + b)*2]     = (float)mean;
        g_stats[(a*2 + b)*2 + 1] = (float)(1.0 / sqrt(var + 1e-5));
    }
}

// ---------------- K5: groupnorm + up-proj + combine ----------------
__global__ void k_comb(const float* __restrict__ gnw,  const float* __restrict__ gnb,
                       const float* __restrict__ gnws, const float* __restrict__ gnbs,
                       const float* __restrict__ wup,  const float* __restrict__ bup,
                       const float* __restrict__ wups, const float* __restrict__ bups) {
    __shared__ float s[4096 + 128 + 128 + 8];
    float* s_wup  = s;              // 2048 (64x32)
    float* s_wups = s + 2048;       // 2048
    float* s_gnw  = s + 4096;       // 32
    float* s_gnb  = s + 4128;
    float* s_gnws = s + 4160;
    float* s_gnbs = s + 4192;
    float* s_bup  = s + 4224;       // 64
    float* s_bups = s + 4288;       // 64
    float* s_st   = s + 4352;       // 8

    int tid = threadIdx.x;
    for (int i = tid; i < 2048; i += 256) { s_wup[i] = wup[i]; s_wups[i] = wups[i]; }
    if (tid < 32) { s_gnw[tid] = gnw[tid]; s_gnb[tid] = gnb[tid];
                    s_gnws[tid] = gnws[tid]; s_gnbs[tid] = gnbs[tid]; }
    if (tid < 64) { s_bup[tid] = bup[tid]; s_bups[tid] = bups[tid]; }
    if (tid < 8)  { s_st[tid] = g_stats[tid]; }
    __syncthreads();

    int idx = blockIdx.x * blockDim.x + tid;
    if (idx >= NB*64*NN) return;
    int n = idx % NN;
    int rest = idx / NN;
    int o = rest % 64;
    int b = rest / 64;

    const float* p0 = g_out + ((size_t)(0*NB + b)*NN + n) * 32;  // cross
    const float* p1 = g_out + ((size_t)(1*NB + b)*NN + n) * 32;  // self
    float mu0 = s_st[b*2],       rs0 = s_st[b*2 + 1];
    float mu1 = s_st[4 + b*2],   rs1 = s_st[4 + b*2 + 1];

    float a0 = s_bup[o], a1 = s_bups[o];
    #pragma unroll
    for (int c = 0; c < 32; c++) {
        float xn0 = (p0[c] - mu0) * rs0 * s_gnw[c]  + s_gnb[c];
        float xn1 = (p1[c] - mu1) * rs1 * s_gnws[c] + s_gnbs[c];
        a0 += s_wup[o*32 + c]  * xn0;
        a1 += s_wups[o*32 + c] * xn1;
    }
    g_comb[((size_t)b*64 + o) * NN + n] = a1 - 0.5f * a0;
}

// ---------------- K6: trilinear upsample + residual ----------------
__global__ void k_final(const float* __restrict__ xc, float* __restrict__ out) {
    int idx = blockIdx.x * blockDim.x + threadIdx.x;
    const int total = NB*64*NFULL;
    if (idx >= total) return;
    int w = idx % WF;
    int rest = idx / WF;
    int h = rest % HF; rest /= HF;
    int t = rest % TF; rest /= TF;
    int c = rest % 64;
    int b = rest / 64;

    float pt = (float)t * ((float)(tT-1)/(float)(TF-1));
    int t0 = (int)floorf(pt); t0 = t0 < 0 ? 0 : (t0 > tT-1 ? tT-1 : t0);
    int t1 = t0+1 > tT-1 ? tT-1 : t0+1;
    float wt = pt - (float)t0;

    float ph = (float)h * ((float)(tH-1)/(float)(HF-1));
    int h0 = (int)floorf(ph); h0 = h0 < 0 ? 0 : (h0 > tH-1 ? tH-1 : h0);
    int h1 = h0+1 > tH-1 ? tH-1 : h0+1;
    float wh = ph - (float)h0;

    float pw = (float)w * ((float)(tW-1)/(float)(WF-1));
    int w0 = (int)floorf(pw); w0 = w0 < 0 ? 0 : (w0 > tW-1 ? tW-1 : w0);
    int w1 = w0+1 > tW-1 ? tW-1 : w0+1;
    float wwf = pw - (float)w0;

    const float* base = g_comb + ((size_t)b*64 + c) * NN;
    float a00 = base[t0*HWt + h0*tW + w0];
    float a01 = base[t0*HWt + h0*tW + w1];
    float a10 = base[t0*HWt + h1*tW + w0];
    float a11 = base[t0*HWt + h1*tW + w1];
    float b00 = base[t1*HWt + h0*tW + w0];
    float b01 = base[t1*HWt + h0*tW + w1];
    float b10 = base[t1*HWt + h1*tW + w0];
    float b11 = base[t1*HWt + h1*tW + w1];

    float va0 = a00 + (a01 - a00)*wwf;
    float va1 = a10 + (a11 - a10)*wwf;
    float vb0 = b00 + (b01 - b00)*wwf;
    float vb1 = b10 + (b11 - b10)*wwf;
    float va = va0 + (va1 - va0)*wh;
    float vb = vb0 + (vb1 - vb0)*wh;
    float v = va + (vb - va)*wt;

    out[idx] = v + xc[idx];
}

// ---------------- launch ----------------
extern "C" void kernel_launch(void* const* d_in, const int* in_sizes, int n_in,
                              void* d_out, int out_size) {
    const float* x    = (const float*)d_in[0];
    const float* xc   = (const float*)d_in[1];
    const float* wd   = (const float*)d_in[2];
    const float* bd   = (const float*)d_in[3];
    const float* wdc  = (const float*)d_in[4];
    const float* bdc  = (const float*)d_in[5];
    const float* wq   = (const float*)d_in[6];
    const float* bq   = (const float*)d_in[7];
    const float* wk   = (const float*)d_in[8];
    const float* bk   = (const float*)d_in[9];
    const float* wv   = (const float*)d_in[10];
    const float* bv   = (const float*)d_in[11];
    const float* wqs  = (const float*)d_in[12];
    const float* bqs  = (const float*)d_in[13];
    const float* wks  = (const float*)d_in[14];
    const float* bks  = (const float*)d_in[15];
    const float* wvs  = (const float*)d_in[16];
    const float* bvs  = (const float*)d_in[17];
    const float* gnw  = (const float*)d_in[18];
    const float* gnb  = (const float*)d_in[19];
    const float* gnws = (const float*)d_in[20];
    const float* gnbs = (const float*)d_in[21];
    const float* wup  = (const float*)d_in[22];
    const float* bup  = (const float*)d_in[23];
    const float* wups = (const float*)d_in[24];
    const float* bups = (const float*)d_in[25];
    const float* offE = (const float*)d_in[26];
    const float* offC = (const float*)d_in[27];
    float* out = (float*)d_out;

    k_resize_down<<<(2*NB*CIN*NN + 255)/256, 256>>>(x, xc);
    k_proj<<<(NB*NN + 255)/256, 256>>>(wd, bd, wdc, bdc, wq, bq, wk, bk, wv, bv,
                                       wqs, bqs, wks, bks, wvs, bvs, offE, offC);
    dim3 ag(NN/QT, NB, 2);
    k_attn<<<ag, QT>>>();
    k_stats<<<4, 256>>>();
    k_comb<<<(NB*64*NN + 255)/256, 256>>>(gnw, gnb, gnws, gnbs, wup, bup, wups, bups);
    k_final<<<(NB*64*NFULL + 255)/256, 256>>>(xc, out);
}

// round 2
// speedup vs baseline: 1.4572x; 1.4572x over previous
#include <cuda_runtime.h>
#include <math.h>

#define NB 2
#define CIN 64
#define TF 16
#define HF 48
#define WF 48
#define tT 8
#define tH 24
#define tW 24
#define NN 4608             // tT*tH*tW
#define HWt 576             // tH*tW
#define NFULL 36864         // TF*HF*WF
#define KSPLIT 4
#define KCHUNK (NN/KSPLIT)  // 1152

// -------- scratch (device globals; no allocations) --------
__device__ float g_xr[2*NB*CIN*NN];       // [src][b][c][n]
__device__ float g_q  [NB*NN*16];
__device__ float g_k  [NB*NN*16];
__device__ float g_v  [NB*NN*32];
__device__ float g_qsa[NB*NN*16];
__device__ float g_ksa[NB*NN*16];
__device__ float g_vsa[NB*NN*32];
__device__ float g_pm  [2*NB*KSPLIT*NN];        // partial max
__device__ float g_pd  [2*NB*KSPLIT*NN];        // partial denom
__device__ float g_pacc[2*NB*KSPLIT*NN*32];     // partial acc
__device__ float g_out[2*NB*NN*32];       // [attn][b][n][c]
__device__ float g_comb[NB*64*NN];        // [b][c][n]
__device__ double g_red[8];               // [attn][b][{sum,sumsq}]

// ---------------- K1: trilinear downsample (+ zero g_red) ----------------
__global__ void k_resize_down(const float* __restrict__ x, const float* __restrict__ xc) {
    int idx = blockIdx.x * blockDim.x + threadIdx.x;
    if (blockIdx.x == 0 && threadIdx.x < 8) g_red[threadIdx.x] = 0.0;
    const int total = 2*NB*CIN*NN;
    if (idx >= total) return;
    int n = idx % NN;
    int rest = idx / NN;
    int c = rest % CIN; rest /= CIN;
    int b = rest % NB;
    int src = rest / NB;

    int ww = n % tW;
    int hh = (n / tW) % tH;
    int tt = n / HWt;

    float pt = (float)tt * ((float)(TF-1)/(float)(tT-1));
    int t0 = (int)floorf(pt); t0 = t0 < 0 ? 0 : (t0 > TF-1 ? TF-1 : t0);
    int t1 = t0+1 > TF-1 ? TF-1 : t0+1;
    float wt = pt - (float)t0;

    float ph = (float)hh * ((float)(HF-1)/(float)(tH-1));
    int h0 = (int)floorf(ph); h0 = h0 < 0 ? 0 : (h0 > HF-1 ? HF-1 : h0);
    int h1 = h0+1 > HF-1 ? HF-1 : h0+1;
    float wh = ph - (float)h0;

    float pw = (float)ww * ((float)(WF-1)/(float)(tW-1));
    int w0 = (int)floorf(pw); w0 = w0 < 0 ? 0 : (w0 > WF-1 ? WF-1 : w0);
    int w1 = w0+1 > WF-1 ? WF-1 : w0+1;
    float wwf = pw - (float)w0;

    const float* sp = src ? xc : x;
    const float* base = sp + (size_t)(b*CIN + c) * NFULL;

    float a00 = base[t0*HF*WF + h0*WF + w0];
    float a01 = base[t0*HF*WF + h0*WF + w1];
    float a10 = base[t0*HF*WF + h1*WF + w0];
    float a11 = base[t0*HF*WF + h1*WF + w1];
    float b00 = base[t1*HF*WF + h0*WF + w0];
    float b01 = base[t1*HF*WF + h0*WF + w1];
    float b10 = base[t1*HF*WF + h1*WF + w0];
    float b11 = base[t1*HF*WF + h1*WF + w1];

    float va0 = a00 + (a01 - a00)*wwf;
    float va1 = a10 + (a11 - a10)*wwf;
    float vb0 = b00 + (b01 - b00)*wwf;
    float vb1 = b10 + (b11 - b10)*wwf;
    float va = va0 + (va1 - va0)*wh;
    float vb = vb0 + (vb1 - vb0)*wh;
    g_xr[idx] = va + (vb - va)*wt;
}

// ---------------- K2: down-proj + all projections + RoPE ----------------
__global__ void k_proj(const float* __restrict__ wd,  const float* __restrict__ bd,
                       const float* __restrict__ wdc, const float* __restrict__ bdc,
                       const float* __restrict__ wq,  const float* __restrict__ bq,
                       const float* __restrict__ wk,  const float* __restrict__ bk,
                       const float* __restrict__ wv,  const float* __restrict__ bv,
                       const float* __restrict__ wqs, const float* __restrict__ bqs,
                       const float* __restrict__ wks, const float* __restrict__ bks,
                       const float* __restrict__ wvs, const float* __restrict__ bvs,
                       const float* __restrict__ offE, const float* __restrict__ offC) {
    __shared__ float s[8192 + 192];
    float* s_wd  = s;           // 2048
    float* s_wdc = s + 2048;    // 2048
    float* s_wq  = s + 4096;    // 512
    float* s_wk  = s + 4608;    // 512
    float* s_wqs = s + 5120;    // 512
    float* s_wks = s + 5632;    // 512
    float* s_wv  = s + 6144;    // 1024
    float* s_wvs = s + 7168;    // 1024
    float* s_b   = s + 8192;    // 192 biases

    int tid = threadIdx.x;
    for (int i = tid; i < 2048; i += 128) { s_wd[i] = wd[i]; s_wdc[i] = wdc[i]; }
    for (int i = tid; i < 512;  i += 128) { s_wq[i] = wq[i]; s_wk[i] = wk[i]; s_wqs[i] = wqs[i]; s_wks[i] = wks[i]; }
    for (int i = tid; i < 1024; i += 128) { s_wv[i] = wv[i]; s_wvs[i] = wvs[i]; }
    if (tid < 32) { s_b[tid] = bd[tid];  s_b[32+tid]  = bdc[tid];
                    s_b[128+tid] = bv[tid]; s_b[160+tid] = bvs[tid]; }
    if (tid < 16) { s_b[64+tid] = bq[tid];  s_b[80+tid]  = bk[tid];
                    s_b[96+tid] = bqs[tid]; s_b[112+tid] = bks[tid]; }
    __syncthreads();

    int gid = blockIdx.x * blockDim.x + tid;
    if (gid >= NB*NN) return;
    int b = gid / NN, n = gid % NN;

    float xd[32], xcd[32];
    #pragma unroll
    for (int o = 0; o < 32; o++) { xd[o] = s_b[o]; xcd[o] = s_b[32+o]; }

    const float* xrx = g_xr + ((size_t)(0*NB + b) * CIN) * NN + n;
    const float* xrc = g_xr + ((size_t)(1*NB + b) * CIN) * NN + n;
    for (int c = 0; c < 64; c++) {
        float vx = xrx[(size_t)c * NN];
        float vc = xrc[(size_t)c * NN];
        #pragma unroll
        for (int o = 0; o < 32; o++) {
            xd[o]  += s_wd [o*64 + c] * vx;
            xcd[o] += s_wdc[o*64 + c] * vc;
        }
    }

    // RoPE factors for this token's t
    int t = n / HWt;
    float se[8], ce[8], scf[8], ccf[8];
    #pragma unroll
    for (int i = 0; i < 8; i++) {
        float invf = powf(10000.0f, -(float)i / 8.0f);
        float f = (float)t * invf;
        float sv = sinf(f), cv = cosf(f);
        float oe = offE[i*500 + t];
        float oc = offC[i*500 + t];
        se[i]  = sv + oe; ce[i]  = cv + oe;
        scf[i] = sv + oc; ccf[i] = cv + oc;
    }

    float pre[16];
    // q = rope(wq @ xd, sin_e/cos_e)
    #pragma unroll
    for (int o = 0; o < 16; o++) {
        float a = s_b[64+o];
        #pragma unroll
        for (int c = 0; c < 32; c++) a += s_wq[o*32+c] * xd[c];
        pre[o] = a;
    }
    {
        float* qo = g_q + ((size_t)b*NN + n) * 16;
        #pragma unroll
        for (int i = 0; i < 8; i++) {
            qo[i]   = pre[i]*ce[i]   - pre[i+8]*se[i];
            qo[i+8] = pre[i+8]*ce[i] + pre[i]*se[i];
        }
    }
    // k = rope(wk @ xcd, sin_c/cos_c)
    #pragma unroll
    for (int o = 0; o < 16; o++) {
        float a = s_b[80+o];
        #pragma unroll
        for (int c = 0; c < 32; c++) a += s_wk[o*32+c] * xcd[c];
        pre[o] = a;
    }
    {
        float* ko = g_k + ((size_t)b*NN + n) * 16;
        #pragma unroll
        for (int i = 0; i < 8; i++) {
            ko[i]   = pre[i]*ccf[i]   - pre[i+8]*scf[i];
            ko[i+8] = pre[i+8]*ccf[i] + pre[i]*scf[i];
        }
    }
    // q_sa = rope(wqs @ xcd, sin_e/cos_e)
    #pragma unroll
    for (int o = 0; o < 16; o++) {
        float a = s_b[96+o];
        #pragma unroll
        for (int c = 0; c < 32; c++) a += s_wqs[o*32+c] * xcd[c];
        pre[o] = a;
    }
    {
        float* qo = g_qsa + ((size_t)b*NN + n) * 16;
        #pragma unroll
        for (int i = 0; i < 8; i++) {
            qo[i]   = pre[i]*ce[i]   - pre[i+8]*se[i];
            qo[i+8] = pre[i+8]*ce[i] + pre[i]*se[i];
        }
    }
    // k_sa = rope(wks @ xcd, sin_e/cos_e)
    #pragma unroll
    for (int o = 0; o < 16; o++) {
        float a = s_b[112+o];
        #pragma unroll
        for (int c = 0; c < 32; c++) a += s_wks[o*32+c] * xcd[c];
        pre[o] = a;
    }
    {
        float* ko = g_ksa + ((size_t)b*NN + n) * 16;
        #pragma unroll
        for (int i = 0; i < 8; i++) {
            ko[i]   = pre[i]*ce[i]   - pre[i+8]*se[i];
            ko[i+8] = pre[i+8]*ce[i] + pre[i]*se[i];
        }
    }
    // v = wv @ xcd ; v_sa = wvs @ xcd
    {
        float* vo  = g_v   + ((size_t)b*NN + n) * 32;
        float* vso = g_vsa + ((size_t)b*NN + n) * 32;
        #pragma unroll
        for (int o = 0; o < 32; o++) {
            float a = s_b[128+o], a2 = s_b[160+o];
            #pragma unroll
            for (int c = 0; c < 32; c++) {
                a  += s_wv [o*32+c] * xcd[c];
                a2 += s_wvs[o*32+c] * xcd[c];
            }
            vo[o] = a; vso[o] = a2;
        }
    }
}

// ---------------- K3: flash attention, split-K (1 query / thread) ----------------
#define QT 128
#define MT 128
__global__ void __launch_bounds__(QT) k_attn() {
    int zz = blockIdx.z;               // a*NB + b
    int a = zz >> 1;
    int b = zz & 1;
    int kt = blockIdx.y;               // k-chunk
    int n = blockIdx.x * QT + threadIdx.x;

    const float* qp = a ? g_qsa : g_q;
    const float* kp = a ? g_ksa : g_k;
    const float* vp = a ? g_vsa : g_v;

    __shared__ float ks[MT][16];
    __shared__ float vs[MT][32];

    float q[16];
    const float* qrow = qp + ((size_t)b*NN + n) * 16;
    #pragma unroll
    for (int i = 0; i < 16; i++) q[i] = qrow[i];

    float mval = -INFINITY, dsum = 0.f;
    float acc[32];
    #pragma unroll
    for (int c = 0; c < 32; c++) acc[c] = 0.f;

    const int kbeg = kt * KCHUNK;
    for (int mt = kbeg; mt < kbeg + KCHUNK; mt += MT) {
        __syncthreads();
        {
            const float4* krow = (const float4*)(kp + ((size_t)b*NN + mt + threadIdx.x) * 16);
            float4* kdst = (float4*)ks[threadIdx.x];
            #pragma unroll
            for (int i = 0; i < 4; i++) kdst[i] = krow[i];
            const float4* vrow = (const float4*)(vp + ((size_t)b*NN + mt + threadIdx.x) * 32);
            float4* vdst = (float4*)vs[threadIdx.x];
            #pragma unroll
            for (int i = 0; i < 8; i++) vdst[i] = vrow[i];
        }
        __syncthreads();

        #pragma unroll 2
        for (int mm = 0; mm < MT; mm++) {
            float s0 = 0.f, s1 = 0.f, s2 = 0.f, s3 = 0.f;
            #pragma unroll
            for (int i = 0; i < 4; i++) {
                s0 += q[i]      * ks[mm][i];
                s1 += q[4 + i]  * ks[mm][4 + i];
                s2 += q[8 + i]  * ks[mm][8 + i];
                s3 += q[12 + i] * ks[mm][12 + i];
            }
            float sc = (s0 + s1 + s2 + s3) * 0.5f;
            if (sc > mval) {
                float corr = __expf(mval - sc);
                dsum *= corr;
                #pragma unroll
                for (int c = 0; c < 32; c++) acc[c] *= corr;
                mval = sc;
            }
            float p = __expf(sc - mval);
            dsum += p;
            #pragma unroll
            for (int c = 0; c < 32; c++) acc[c] += p * vs[mm][c];
        }
    }

    size_t pidx = ((size_t)zz * KSPLIT + kt) * NN + n;
    g_pm[pidx] = mval;
    g_pd[pidx] = dsum;
    float* pa = g_pacc + pidx * 32;
    #pragma unroll
    for (int c = 0; c < 32; c++) pa[c] = acc[c];
}

// ---------------- K3b: merge split-K partials + groupnorm reduction ----------------
__global__ void __launch_bounds__(256) k_merge() {
    int zz = blockIdx.y;               // a*NB + b
    int n = blockIdx.x * 256 + threadIdx.x;

    float m[KSPLIT];
    float M = -INFINITY;
    #pragma unroll
    for (int k = 0; k < KSPLIT; k++) {
        m[k] = g_pm[((size_t)zz * KSPLIT + k) * NN + n];
        M = fmaxf(M, m[k]);
    }
    float w[KSPLIT];
    float d = 0.f;
    #pragma unroll
    for (int k = 0; k < KSPLIT; k++) {
        w[k] = __expf(m[k] - M);
        d += g_pd[((size_t)zz * KSPLIT + k) * NN + n] * w[k];
    }
    float inv = 1.0f / d;

    float* orow = g_out + ((size_t)zz * NN + n) * 32;
    float lsum = 0.f, lsum2 = 0.f;
    #pragma unroll
    for (int c = 0; c < 32; c++) {
        float acc = 0.f;
        #pragma unroll
        for (int k = 0; k < KSPLIT; k++)
            acc += g_pacc[(((size_t)zz * KSPLIT + k) * NN + n) * 32 + c] * w[k];
        float o = acc * inv;
        orow[c] = o;
        lsum += o;
        lsum2 += o * o;
    }

    // block reduce for groupnorm stats
    __shared__ double rs[256], rs2[256];
    rs[threadIdx.x] = (double)lsum;
    rs2[threadIdx.x] = (double)lsum2;
    __syncthreads();
    for (int st = 128; st > 0; st >>= 1) {
        if (threadIdx.x < st) {
            rs[threadIdx.x]  += rs[threadIdx.x + st];
            rs2[threadIdx.x] += rs2[threadIdx.x + st];
        }
        __syncthreads();
    }
    if (threadIdx.x == 0) {
        atomicAdd(&g_red[zz*2],     rs[0]);
        atomicAdd(&g_red[zz*2 + 1], rs2[0]);
    }
}

// ---------------- K5: groupnorm + up-proj + combine ----------------
__global__ void k_comb(const float* __restrict__ gnw,  const float* __restrict__ gnb,
                       const float* __restrict__ gnws, const float* __restrict__ gnbs,
                       const float* __restrict__ wup,  const float* __restrict__ bup,
                       const float* __restrict__ wups, const float* __restrict__ bups) {
    __shared__ float s[4096 + 128 + 128 + 8];
    float* s_wup  = s;              // 2048 (64x32)
    float* s_wups = s + 2048;       // 2048
    float* s_gnw  = s + 4096;       // 32
    float* s_gnb  = s + 4128;
    float* s_gnws = s + 4160;
    float* s_gnbs = s + 4192;
    float* s_bup  = s + 4224;       // 64
    float* s_bups = s + 4288;       // 64
    float* s_st   = s + 4352;       // 8: mean/rstd per zz

    int tid = threadIdx.x;
    for (int i = tid; i < 2048; i += 256) { s_wup[i] = wup[i]; s_wups[i] = wups[i]; }
    if (tid < 32) { s_gnw[tid] = gnw[tid]; s_gnb[tid] = gnb[tid];
                    s_gnws[tid] = gnws[tid]; s_gnbs[tid] = gnbs[tid]; }
    if (tid < 64) { s_bup[tid] = bup[tid]; s_bups[tid] = bups[tid]; }
    if (tid < 4) {
        const double M = (double)NN * 32.0;
        double mean = g_red[tid*2] / M;
        double var  = g_red[tid*2 + 1] / M - mean * mean;
        s_st[tid*2]     = (float)mean;
        s_st[tid*2 + 1] = (float)(1.0 / sqrt(var + 1e-5));
    }
    __syncthreads();

    int idx = blockIdx.x * blockDim.x + tid;
    if (idx >= NB*64*NN) return;
    int n = idx % NN;
    int rest = idx / NN;
    int o = rest % 64;
    int b = rest / 64;

    const float* p0 = g_out + ((size_t)(0*NB + b)*NN + n) * 32;  // cross
    const float* p1 = g_out + ((size_t)(1*NB + b)*NN + n) * 32;  // self
    float mu0 = s_st[b*2],       rs0 = s_st[b*2 + 1];
    float mu1 = s_st[4 + b*2],   rs1 = s_st[4 + b*2 + 1];

    float a0 = s_bup[o], a1 = s_bups[o];
    #pragma unroll
    for (int c = 0; c < 32; c++) {
        float xn0 = (p0[c] - mu0) * rs0 * s_gnw[c]  + s_gnb[c];
        float xn1 = (p1[c] - mu1) * rs1 * s_gnws[c] + s_gnbs[c];
        a0 += s_wup[o*32 + c]  * xn0;
        a1 += s_wups[o*32 + c] * xn1;
    }
    g_comb[((size_t)b*64 + o) * NN + n] = a1 - 0.5f * a0;
}

// ---------------- K6: trilinear upsample + residual ----------------
__global__ void k_final(const float* __restrict__ xc, float* __restrict__ out) {
    int idx = blockIdx.x * blockDim.x + threadIdx.x;
    const int total = NB*64*NFULL;
    if (idx >= total) return;
    int w = idx % WF;
    int rest = idx / WF;
    int h = rest % HF; rest /= HF;
    int t = rest % TF; rest /= TF;
    int c = rest % 64;
    int b = rest / 64;

    float pt = (float)t * ((float)(tT-1)/(float)(TF-1));
    int t0 = (int)floorf(pt); t0 = t0 < 0 ? 0 : (t0 > tT-1 ? tT-1 : t0);
    int t1 = t0+1 > tT-1 ? tT-1 : t0+1;
    float wt = pt - (float)t0;

    float ph = (float)h * ((float)(tH-1)/(float)(HF-1));
    int h0 = (int)floorf(ph); h0 = h0 < 0 ? 0 : (h0 > tH-1 ? tH-1 : h0);
    int h1 = h0+1 > tH-1 ? tH-1 : h0+1;
    float wh = ph - (float)h0;

    float pw = (float)w * ((float)(tW-1)/(float)(WF-1));
    int w0 = (int)floorf(pw); w0 = w0 < 0 ? 0 : (w0 > tW-1 ? tW-1 : w0);
    int w1 = w0+1 > tW-1 ? tW-1 : w0+1;
    float wwf = pw - (float)w0;

    const float* base = g_comb + ((size_t)b*64 + c) * NN;
    float a00 = base[t0*HWt + h0*tW + w0];
    float a01 = base[t0*HWt + h0*tW + w1];
    float a10 = base[t0*HWt + h1*tW + w0];
    float a11 = base[t0*HWt + h1*tW + w1];
    float b00 = base[t1*HWt + h0*tW + w0];
    float b01 = base[t1*HWt + h0*tW + w1];
    float b10 = base[t1*HWt + h1*tW + w0];
    float b11 = base[t1*HWt + h1*tW + w1];

    float va0 = a00 + (a01 - a00)*wwf;
    float va1 = a10 + (a11 - a10)*wwf;
    float vb0 = b00 + (b01 - b00)*wwf;
    float vb1 = b10 + (b11 - b10)*wwf;
    float va = va0 + (va1 - va0)*wh;
    float vb = vb0 + (vb1 - vb0)*wh;
    float v = va + (vb - va)*wt;

    out[idx] = v + xc[idx];
}

// ---------------- launch ----------------
extern "C" void kernel_launch(void* const* d_in, const int* in_sizes, int n_in,
                              void* d_out, int out_size) {
    const float* x    = (const float*)d_in[0];
    const float* xc   = (const float*)d_in[1];
    const float* wd   = (const float*)d_in[2];
    const float* bd   = (const float*)d_in[3];
    const float* wdc  = (const float*)d_in[4];
    const float* bdc  = (const float*)d_in[5];
    const float* wq   = (const float*)d_in[6];
    const float* bq   = (const float*)d_in[7];
    const float* wk   = (const float*)d_in[8];
    const float* bk   = (const float*)d_in[9];
    const float* wv   = (const float*)d_in[10];
    const float* bv   = (const float*)d_in[11];
    const float* wqs  = (const float*)d_in[12];
    const float* bqs  = (const float*)d_in[13];
    const float* wks  = (const float*)d_in[14];
    const float* bks  = (const float*)d_in[15];
    const float* wvs  = (const float*)d_in[16];
    const float* bvs  = (const float*)d_in[17];
    const float* gnw  = (const float*)d_in[18];
    const float* gnb  = (const float*)d_in[19];
    const float* gnws = (const float*)d_in[20];
    const float* gnbs = (const float*)d_in[21];
    const float* wup  = (const float*)d_in[22];
    const float* bup  = (const float*)d_in[23];
    const float* wups = (const float*)d_in[24];
    const float* bups = (const float*)d_in[25];
    const float* offE = (const float*)d_in[26];
    const float* offC = (const float*)d_in[27];
    float* out = (float*)d_out;

    k_resize_down<<<(2*NB*CIN*NN + 255)/256, 256>>>(x, xc);
    k_proj<<<(NB*NN + 127)/128, 128>>>(wd, bd, wdc, bdc, wq, bq, wk, bk, wv, bv,
                                       wqs, bqs, wks, bks, wvs, bvs, offE, offC);
    dim3 ag(NN/QT, KSPLIT, NB*2);
    k_attn<<<ag, QT>>>();
    dim3 mg(NN/256, NB*2, 1);
    k_merge<<<mg, 256>>>();
    k_comb<<<(NB*64*NN + 255)/256, 256>>>(gnw, gnb, gnws, gnbs, wup, bup, wups, bups);
    k_final<<<(NB*64*NFULL + 255)/256, 256>>>(xc, out);
}

// round 3
// speedup vs baseline: 1.5866x; 1.0888x over previous
#include <cuda_runtime.h>
#include <math.h>

#define NB 2
#define CIN 64
#define TF 16
#define HF 48
#define WF 48
#define tT 8
#define tH 24
#define tW 24
#define NN 4608             // tT*tH*tW
#define HWt 576             // tH*tW
#define NFULL 36864         // TF*HF*WF
#define KSPLIT 6
#define KCHUNK (NN/KSPLIT)  // 768

typedef unsigned long long ull;

__device__ __forceinline__ ull pack2(float lo, float hi) {
    ull r; asm("mov.b64 %0, {%1,%2};" : "=l"(r) : "f"(lo), "f"(hi)); return r;
}
__device__ __forceinline__ void unpack2(ull v, float& lo, float& hi) {
    asm("mov.b64 {%0,%1}, %2;" : "=f"(lo), "=f"(hi) : "l"(v));
}
__device__ __forceinline__ ull fma2(ull a, ull b, ull c) {
    ull d; asm("fma.rn.f32x2 %0, %1, %2, %3;" : "=l"(d) : "l"(a), "l"(b), "l"(c)); return d;
}
__device__ __forceinline__ ull mul2(ull a, ull b) {
    ull d; asm("mul.rn.f32x2 %0, %1, %2;" : "=l"(d) : "l"(a), "l"(b)); return d;
}

// -------- scratch (device globals; no allocations) --------
__device__ float g_xr[2*NB*CIN*NN];       // [src][b][c][n]
__device__ float g_q  [NB*NN*16];
__device__ float g_k  [NB*NN*16];
__device__ float g_v  [NB*NN*32];
__device__ float g_qsa[NB*NN*16];
__device__ float g_ksa[NB*NN*16];
__device__ float g_vsa[NB*NN*32];
__device__ float g_pm  [2*NB*KSPLIT*NN];        // partial max
__device__ float g_pd  [2*NB*KSPLIT*NN];        // partial denom
__device__ float g_pacc[2*NB*KSPLIT*NN*32];     // partial acc
__device__ float g_out[2*NB*NN*32];       // [attn][b][n][c]
__device__ float g_comb[NB*64*NN];        // [b][c][n]
__device__ double g_red[8];               // [attn][b][{sum,sumsq}]

// ---------------- K1: trilinear downsample (+ zero g_red) ----------------
__global__ void k_resize_down(const float* __restrict__ x, const float* __restrict__ xc) {
    int idx = blockIdx.x * blockDim.x + threadIdx.x;
    if (blockIdx.x == 0 && threadIdx.x < 8) g_red[threadIdx.x] = 0.0;
    const int total = 2*NB*CIN*NN;
    if (idx >= total) return;
    int n = idx % NN;
    int rest = idx / NN;
    int c = rest % CIN; rest /= CIN;
    int b = rest % NB;
    int src = rest / NB;

    int ww = n % tW;
    int hh = (n / tW) % tH;
    int tt = n / HWt;

    float pt = (float)tt * ((float)(TF-1)/(float)(tT-1));
    int t0 = (int)floorf(pt); t0 = t0 < 0 ? 0 : (t0 > TF-1 ? TF-1 : t0);
    int t1 = t0+1 > TF-1 ? TF-1 : t0+1;
    float wt = pt - (float)t0;

    float ph = (float)hh * ((float)(HF-1)/(float)(tH-1));
    int h0 = (int)floorf(ph); h0 = h0 < 0 ? 0 : (h0 > HF-1 ? HF-1 : h0);
    int h1 = h0+1 > HF-1 ? HF-1 : h0+1;
    float wh = ph - (float)h0;

    float pw = (float)ww * ((float)(WF-1)/(float)(tW-1));
    int w0 = (int)floorf(pw); w0 = w0 < 0 ? 0 : (w0 > WF-1 ? WF-1 : w0);
    int w1 = w0+1 > WF-1 ? WF-1 : w0+1;
    float wwf = pw - (float)w0;

    const float* sp = src ? xc : x;
    const float* base = sp + (size_t)(b*CIN + c) * NFULL;

    float a00 = base[t0*HF*WF + h0*WF + w0];
    float a01 = base[t0*HF*WF + h0*WF + w1];
    float a10 = base[t0*HF*WF + h1*WF + w0];
    float a11 = base[t0*HF*WF + h1*WF + w1];
    float b00 = base[t1*HF*WF + h0*WF + w0];
    float b01 = base[t1*HF*WF + h0*WF + w1];
    float b10 = base[t1*HF*WF + h1*WF + w0];
    float b11 = base[t1*HF*WF + h1*WF + w1];

    float va0 = a00 + (a01 - a00)*wwf;
    float va1 = a10 + (a11 - a10)*wwf;
    float vb0 = b00 + (b01 - b00)*wwf;
    float vb1 = b10 + (b11 - b10)*wwf;
    float va = va0 + (va1 - va0)*wh;
    float vb = vb0 + (vb1 - vb0)*wh;
    g_xr[idx] = va + (vb - va)*wt;
}

// ---------------- K2: down-proj + all projections + RoPE ----------------
__global__ void k_proj(const float* __restrict__ wd,  const float* __restrict__ bd,
                       const float* __restrict__ wdc, const float* __restrict__ bdc,
                       const float* __restrict__ wq,  const float* __restrict__ bq,
                       const float* __restrict__ wk,  const float* __restrict__ bk,
                       const float* __restrict__ wv,  const float* __restrict__ bv,
                       const float* __restrict__ wqs, const float* __restrict__ bqs,
                       const float* __restrict__ wks, const float* __restrict__ bks,
                       const float* __restrict__ wvs, const float* __restrict__ bvs,
                       const float* __restrict__ offE, const float* __restrict__ offC) {
    __shared__ float s[8192 + 192];
    float* s_wd  = s;           // 2048
    float* s_wdc = s + 2048;    // 2048
    float* s_wq  = s + 4096;    // 512
    float* s_wk  = s + 4608;    // 512
    float* s_wqs = s + 5120;    // 512
    float* s_wks = s + 5632;    // 512
    float* s_wv  = s + 6144;    // 1024
    float* s_wvs = s + 7168;    // 1024
    float* s_b   = s + 8192;    // 192 biases

    int tid = threadIdx.x;
    for (int i = tid; i < 2048; i += 64) { s_wd[i] = wd[i]; s_wdc[i] = wdc[i]; }
    for (int i = tid; i < 512;  i += 64) { s_wq[i] = wq[i]; s_wk[i] = wk[i]; s_wqs[i] = wqs[i]; s_wks[i] = wks[i]; }
    for (int i = tid; i < 1024; i += 64) { s_wv[i] = wv[i]; s_wvs[i] = wvs[i]; }
    if (tid < 32) { s_b[tid] = bd[tid];  s_b[32+tid]  = bdc[tid];
                    s_b[128+tid] = bv[tid]; s_b[160+tid] = bvs[tid]; }
    if (tid < 16) { s_b[64+tid] = bq[tid];  s_b[80+tid]  = bk[tid];
                    s_b[96+tid] = bqs[tid]; s_b[112+tid] = bks[tid]; }
    __syncthreads();

    int gid = blockIdx.x * blockDim.x + tid;
    if (gid >= NB*NN) return;
    int b = gid / NN, n = gid % NN;

    float xd[32], xcd[32];
    #pragma unroll
    for (int o = 0; o < 32; o++) { xd[o] = s_b[o]; xcd[o] = s_b[32+o]; }

    const float* xrx = g_xr + ((size_t)(0*NB + b) * CIN) * NN + n;
    const float* xrc = g_xr + ((size_t)(1*NB + b) * CIN) * NN + n;
    for (int c = 0; c < 64; c++) {
        float vx = xrx[(size_t)c * NN];
        float vc = xrc[(size_t)c * NN];
        #pragma unroll
        for (int o = 0; o < 32; o++) {
            xd[o]  += s_wd [o*64 + c] * vx;
            xcd[o] += s_wdc[o*64 + c] * vc;
        }
    }

    // RoPE factors for this token's t
    int t = n / HWt;
    float se[8], ce[8], scf[8], ccf[8];
    #pragma unroll
    for (int i = 0; i < 8; i++) {
        float invf = powf(10000.0f, -(float)i / 8.0f);
        float f = (float)t * invf;
        float sv = sinf(f), cv = cosf(f);
        float oe = offE[i*500 + t];
        float oc = offC[i*500 + t];
        se[i]  = sv + oe; ce[i]  = cv + oe;
        scf[i] = sv + oc; ccf[i] = cv + oc;
    }

    float pre[16];
    // q = rope(wq @ xd, sin_e/cos_e)
    #pragma unroll
    for (int o = 0; o < 16; o++) {
        float a = s_b[64+o];
        #pragma unroll
        for (int c = 0; c < 32; c++) a += s_wq[o*32+c] * xd[c];
        pre[o] = a;
    }
    {
        float* qo = g_q + ((size_t)b*NN + n) * 16;
        #pragma unroll
        for (int i = 0; i < 8; i++) {
            qo[i]   = pre[i]*ce[i]   - pre[i+8]*se[i];
            qo[i+8] = pre[i+8]*ce[i] + pre[i]*se[i];
        }
    }
    // k = rope(wk @ xcd, sin_c/cos_c)
    #pragma unroll
    for (int o = 0; o < 16; o++) {
        float a = s_b[80+o];
        #pragma unroll
        for (int c = 0; c < 32; c++) a += s_wk[o*32+c] * xcd[c];
        pre[o] = a;
    }
    {
        float* ko = g_k + ((size_t)b*NN + n) * 16;
        #pragma unroll
        for (int i = 0; i < 8; i++) {
            ko[i]   = pre[i]*ccf[i]   - pre[i+8]*scf[i];
            ko[i+8] = pre[i+8]*ccf[i] + pre[i]*scf[i];
        }
    }
    // q_sa = rope(wqs @ xcd, sin_e/cos_e)
    #pragma unroll
    for (int o = 0; o < 16; o++) {
        float a = s_b[96+o];
        #pragma unroll
        for (int c = 0; c < 32; c++) a += s_wqs[o*32+c] * xcd[c];
        pre[o] = a;
    }
    {
        float* qo = g_qsa + ((size_t)b*NN + n) * 16;
        #pragma unroll
        for (int i = 0; i < 8; i++) {
            qo[i]   = pre[i]*ce[i]   - pre[i+8]*se[i];
            qo[i+8] = pre[i+8]*ce[i] + pre[i]*se[i];
        }
    }
    // k_sa = rope(wks @ xcd, sin_e/cos_e)
    #pragma unroll
    for (int o = 0; o < 16; o++) {
        float a = s_b[112+o];
        #pragma unroll
        for (int c = 0; c < 32; c++) a += s_wks[o*32+c] * xcd[c];
        pre[o] = a;
    }
    {
        float* ko = g_ksa + ((size_t)b*NN + n) * 16;
        #pragma unroll
        for (int i = 0; i < 8; i++) {
            ko[i]   = pre[i]*ce[i]   - pre[i+8]*se[i];
            ko[i+8] = pre[i+8]*ce[i] + pre[i]*se[i];
        }
    }
    // v = wv @ xcd ; v_sa = wvs @ xcd
    {
        float* vo  = g_v   + ((size_t)b*NN + n) * 32;
        float* vso = g_vsa + ((size_t)b*NN + n) * 32;
        #pragma unroll
        for (int o = 0; o < 32; o++) {
            float a = s_b[128+o], a2 = s_b[160+o];
            #pragma unroll
            for (int c = 0; c < 32; c++) {
                a  += s_wv [o*32+c] * xcd[c];
                a2 += s_wvs[o*32+c] * xcd[c];
            }
            vo[o] = a; vso[o] = a2;
        }
    }
}

// ---------------- K3: flash attention, split-K, 2 queries/thread, f32x2 ----------------
#define QT 128
#define MT 128
__global__ void __launch_bounds__(QT) k_attn() {
    int zz = blockIdx.z;               // a*NB + b
    int a = zz >> 1;
    int b = zz & 1;
    int kt = blockIdx.y;               // k-chunk
    int tid = threadIdx.x;
    int n0 = blockIdx.x * (2*QT) + tid;        // query 0
    int n1 = n0 + QT;                          // query 1

    const float* qp = a ? g_qsa : g_q;
    const float* kp = a ? g_ksa : g_k;
    const float* vp = a ? g_vsa : g_v;

    __shared__ __align__(16) float ks[MT][16];
    __shared__ __align__(16) float vs[MT][32];

    ull q0[8], q1[8];
    {
        const ull* qr0 = (const ull*)(qp + ((size_t)b*NN + n0) * 16);
        const ull* qr1 = (const ull*)(qp + ((size_t)b*NN + n1) * 16);
        #pragma unroll
        for (int i = 0; i < 8; i++) { q0[i] = qr0[i]; q1[i] = qr1[i]; }
    }

    float m0 = -INFINITY, m1 = -INFINITY, d0 = 0.f, d1 = 0.f;
    ull acc0[16], acc1[16];
    #pragma unroll
    for (int c = 0; c < 16; c++) { acc0[c] = 0ULL; acc1[c] = 0ULL; }

    const int kbeg = kt * KCHUNK;
    for (int mt = kbeg; mt < kbeg + KCHUNK; mt += MT) {
        __syncthreads();
        {
            const float4* krow = (const float4*)(kp + ((size_t)b*NN + mt + tid) * 16);
            float4* kdst = (float4*)ks[tid];
            #pragma unroll
            for (int i = 0; i < 4; i++) kdst[i] = krow[i];
            const float4* vrow = (const float4*)(vp + ((size_t)b*NN + mt + tid) * 32);
            float4* vdst = (float4*)vs[tid];
            #pragma unroll
            for (int i = 0; i < 8; i++) vdst[i] = vrow[i];
        }
        __syncthreads();

        #pragma unroll 2
        for (int mm = 0; mm < MT; mm++) {
            const ull* k2 = (const ull*)ks[mm];
            ull s0p = 0ULL, s1p = 0ULL;
            #pragma unroll
            for (int i = 0; i < 8; i++) {
                ull kv = k2[i];
                s0p = fma2(q0[i], kv, s0p);
                s1p = fma2(q1[i], kv, s1p);
            }
            float l0, h0, l1, h1;
            unpack2(s0p, l0, h0);
            unpack2(s1p, l1, h1);
            float sc0 = (l0 + h0) * 0.5f;
            float sc1 = (l1 + h1) * 0.5f;

            if (sc0 > m0) {
                float corr = __expf(m0 - sc0);
                d0 *= corr;
                ull cp = pack2(corr, corr);
                #pragma unroll
                for (int c = 0; c < 16; c++) acc0[c] = mul2(acc0[c], cp);
                m0 = sc0;
            }
            if (sc1 > m1) {
                float corr = __expf(m1 - sc1);
                d1 *= corr;
                ull cp = pack2(corr, corr);
                #pragma unroll
                for (int c = 0; c < 16; c++) acc1[c] = mul2(acc1[c], cp);
                m1 = sc1;
            }
            float p0 = __expf(sc0 - m0);
            float p1 = __expf(sc1 - m1);
            d0 += p0; d1 += p1;
            ull pp0 = pack2(p0, p0);
            ull pp1 = pack2(p1, p1);
            const ull* v2 = (const ull*)vs[mm];
            #pragma unroll
            for (int c = 0; c < 16; c++) {
                ull vv = v2[c];
                acc0[c] = fma2(pp0, vv, acc0[c]);
                acc1[c] = fma2(pp1, vv, acc1[c]);
            }
        }
    }

    size_t base = ((size_t)zz * KSPLIT + kt) * NN;
    g_pm[base + n0] = m0;  g_pm[base + n1] = m1;
    g_pd[base + n0] = d0;  g_pd[base + n1] = d1;
    ull* pa0 = (ull*)(g_pacc + (base + n0) * 32);
    ull* pa1 = (ull*)(g_pacc + (base + n1) * 32);
    #pragma unroll
    for (int c = 0; c < 16; c++) { pa0[c] = acc0[c]; pa1[c] = acc1[c]; }
}

// ---------------- K3b: merge split-K partials + groupnorm reduction ----------------
__global__ void __launch_bounds__(128) k_merge() {
    int zz = blockIdx.y;               // a*NB + b
    int n = blockIdx.x * 128 + threadIdx.x;

    float m[KSPLIT];
    float M = -INFINITY;
    #pragma unroll
    for (int k = 0; k < KSPLIT; k++) {
        m[k] = g_pm[((size_t)zz * KSPLIT + k) * NN + n];
        M = fmaxf(M, m[k]);
    }
    float w[KSPLIT];
    float d = 0.f;
    #pragma unroll
    for (int k = 0; k < KSPLIT; k++) {
        w[k] = __expf(m[k] - M);
        d += g_pd[((size_t)zz * KSPLIT + k) * NN + n] * w[k];
    }
    float inv = 1.0f / d;

    float4 acc4[8];
    #pragma unroll
    for (int j = 0; j < 8; j++) acc4[j] = make_float4(0.f, 0.f, 0.f, 0.f);
    #pragma unroll
    for (int k = 0; k < KSPLIT; k++) {
        const float4* pa = (const float4*)(g_pacc + (((size_t)zz * KSPLIT + k) * NN + n) * 32);
        float wk = w[k];
        #pragma unroll
        for (int j = 0; j < 8; j++) {
            float4 v = pa[j];
            acc4[j].x += v.x * wk; acc4[j].y += v.y * wk;
            acc4[j].z += v.z * wk; acc4[j].w += v.w * wk;
        }
    }

    float4* orow = (float4*)(g_out + ((size_t)zz * NN + n) * 32);
    float lsum = 0.f, lsum2 = 0.f;
    #pragma unroll
    for (int j = 0; j < 8; j++) {
        float4 o = make_float4(acc4[j].x*inv, acc4[j].y*inv, acc4[j].z*inv, acc4[j].w*inv);
        orow[j] = o;
        lsum  += o.x + o.y + o.z + o.w;
        lsum2 += o.x*o.x + o.y*o.y + o.z*o.z + o.w*o.w;
    }

    // block reduce for groupnorm stats
    __shared__ double rs[128], rs2[128];
    rs[threadIdx.x] = (double)lsum;
    rs2[threadIdx.x] = (double)lsum2;
    __syncthreads();
    for (int st = 64; st > 0; st >>= 1) {
        if (threadIdx.x < st) {
            rs[threadIdx.x]  += rs[threadIdx.x + st];
            rs2[threadIdx.x] += rs2[threadIdx.x + st];
        }
        __syncthreads();
    }
    if (threadIdx.x == 0) {
        atomicAdd(&g_red[zz*2],     rs[0]);
        atomicAdd(&g_red[zz*2 + 1], rs2[0]);
    }
}

// ---------------- K5: groupnorm + up-proj + combine ----------------
__global__ void k_comb(const float* __restrict__ gnw,  const float* __restrict__ gnb,
                       const float* __restrict__ gnws, const float* __restrict__ gnbs,
                       const float* __restrict__ wup,  const float* __restrict__ bup,
                       const float* __restrict__ wups, const float* __restrict__ bups) {
    __shared__ float s[4096 + 128 + 128 + 8];
    float* s_wup  = s;              // 2048 (64x32)
    float* s_wups = s + 2048;       // 2048
    float* s_gnw  = s + 4096;       // 32
    float* s_gnb  = s + 4128;
    float* s_gnws = s + 4160;
    float* s_gnbs = s + 4192;
    float* s_bup  = s + 4224;       // 64
    float* s_bups = s + 4288;       // 64
    float* s_st   = s + 4352;       // 8: mean/rstd per zz

    int tid = threadIdx.x;
    for (int i = tid; i < 2048; i += 256) { s_wup[i] = wup[i]; s_wups[i] = wups[i]; }
    if (tid < 32) { s_gnw[tid] = gnw[tid]; s_gnb[tid] = gnb[tid];
                    s_gnws[tid] = gnws[tid]; s_gnbs[tid] = gnbs[tid]; }
    if (tid < 64) { s_bup[tid] = bup[tid]; s_bups[tid] = bups[tid]; }
    if (tid < 4) {
        const double M = (double)NN * 32.0;
        double mean = g_red[tid*2] / M;
        double var  = g_red[tid*2 + 1] / M - mean * mean;
        s_st[tid*2]     = (float)mean;
        s_st[tid*2 + 1] = (float)(1.0 / sqrt(var + 1e-5));
    }
    __syncthreads();

    int idx = blockIdx.x * blockDim.x + tid;
    if (idx >= NB*64*NN) return;
    int n = idx % NN;
    int rest = idx / NN;
    int o = rest % 64;
    int b = rest / 64;

    const float* p0 = g_out + ((size_t)(0*NB + b)*NN + n) * 32;  // cross
    const float* p1 = g_out + ((size_t)(1*NB + b)*NN + n) * 32;  // self
    float mu0 = s_st[b*2],       rs0 = s_st[b*2 + 1];
    float mu1 = s_st[4 + b*2],   rs1 = s_st[4 + b*2 + 1];

    float a0 = s_bup[o], a1 = s_bups[o];
    #pragma unroll
    for (int c = 0; c < 32; c++) {
        float xn0 = (p0[c] - mu0) * rs0 * s_gnw[c]  + s_gnb[c];
        float xn1 = (p1[c] - mu1) * rs1 * s_gnws[c] + s_gnbs[c];
        a0 += s_wup[o*32 + c]  * xn0;
        a1 += s_wups[o*32 + c] * xn1;
    }
    g_comb[((size_t)b*64 + o) * NN + n] = a1 - 0.5f * a0;
}

// ---------------- K6: trilinear upsample + residual ----------------
__global__ void k_final(const float* __restrict__ xc, float* __restrict__ out) {
    int idx = blockIdx.x * blockDim.x + threadIdx.x;
    const int total = NB*64*NFULL;
    if (idx >= total) return;
    int w = idx % WF;
    int rest = idx / WF;
    int h = rest % HF; rest /= HF;
    int t = rest % TF; rest /= TF;
    int c = rest % 64;
    int b = rest / 64;

    float pt = (float)t * ((float)(tT-1)/(float)(TF-1));
    int t0 = (int)floorf(pt); t0 = t0 < 0 ? 0 : (t0 > tT-1 ? tT-1 : t0);
    int t1 = t0+1 > tT-1 ? tT-1 : t0+1;
    float wt = pt - (float)t0;

    float ph = (float)h * ((float)(tH-1)/(float)(HF-1));
    int h0 = (int)floorf(ph); h0 = h0 < 0 ? 0 : (h0 > tH-1 ? tH-1 : h0);
    int h1 = h0+1 > tH-1 ? tH-1 : h0+1;
    float wh = ph - (float)h0;

    float pw = (float)w * ((float)(tW-1)/(float)(WF-1));
    int w0 = (int)floorf(pw); w0 = w0 < 0 ? 0 : (w0 > tW-1 ? tW-1 : w0);
    int w1 = w0+1 > tW-1 ? tW-1 : w0+1;
    float wwf = pw - (float)w0;

    const float* base = g_comb + ((size_t)b*64 + c) * NN;
    float a00 = base[t0*HWt + h0*tW + w0];
    float a01 = base[t0*HWt + h0*tW + w1];
    float a10 = base[t0*HWt + h1*tW + w0];
    float a11 = base[t0*HWt + h1*tW + w1];
    float b00 = base[t1*HWt + h0*tW + w0];
    float b01 = base[t1*HWt + h0*tW + w1];
    float b10 = base[t1*HWt + h1*tW + w0];
    float b11 = base[t1*HWt + h1*tW + w1];

    float va0 = a00 + (a01 - a00)*wwf;
    float va1 = a10 + (a11 - a10)*wwf;
    float vb0 = b00 + (b01 - b00)*wwf;
    float vb1 = b10 + (b11 - b10)*wwf;
    float va = va0 + (va1 - va0)*wh;
    float vb = vb0 + (vb1 - vb0)*wh;
    float v = va + (vb - va)*wt;

    out[idx] = v + xc[idx];
}

// ---------------- launch ----------------
extern "C" void kernel_launch(void* const* d_in, const int* in_sizes, int n_in,
                              void* d_out, int out_size) {
    const float* x    = (const float*)d_in[0];
    const float* xc   = (const float*)d_in[1];
    const float* wd   = (const float*)d_in[2];
    const float* bd   = (const float*)d_in[3];
    const float* wdc  = (const float*)d_in[4];
    const float* bdc  = (const float*)d_in[5];
    const float* wq   = (const float*)d_in[6];
    const float* bq   = (const float*)d_in[7];
    const float* wk   = (const float*)d_in[8];
    const float* bk   = (const float*)d_in[9];
    const float* wv   = (const float*)d_in[10];
    const float* bv   = (const float*)d_in[11];
    const float* wqs  = (const float*)d_in[12];
    const float* bqs  = (const float*)d_in[13];
    const float* wks  = (const float*)d_in[14];
    const float* bks  = (const float*)d_in[15];
    const float* wvs  = (const float*)d_in[16];
    const float* bvs  = (const float*)d_in[17];
    const float* gnw  = (const float*)d_in[18];
    const float* gnb  = (const float*)d_in[19];
    const float* gnws = (const float*)d_in[20];
    const float* gnbs = (const float*)d_in[21];
    const float* wup  = (const float*)d_in[22];
    const float* bup  = (const float*)d_in[23];
    const float* wups = (const float*)d_in[24];
    const float* bups = (const float*)d_in[25];
    const float* offE = (const float*)d_in[26];
    const float* offC = (const float*)d_in[27];
    float* out = (float*)d_out;

    k_resize_down<<<(2*NB*CIN*NN + 255)/256, 256>>>(x, xc);
    k_proj<<<(NB*NN + 63)/64, 64>>>(wd, bd, wdc, bdc, wq, bq, wk, bk, wv, bv,
                                    wqs, bqs, wks, bks, wvs, bvs, offE, offC);
    dim3 ag(NN/(2*QT), KSPLIT, NB*2);
    k_attn<<<ag, QT>>>();
    dim3 mg(NN/128, NB*2, 1);
    k_merge<<<mg, 128>>>();
    k_comb<<<(NB*64*NN + 255)/256, 256>>>(gnw, gnb, gnws, gnbs, wup, bup, wups, bups);
    k_final<<<(NB*64*NFULL + 255)/256, 256>>>(xc, out);
}

// round 5
// speedup vs baseline: 2.7497x; 1.7331x over previous
#include <cuda_runtime.h>
#include <cuda_bf16.h>
#include <math.h>

#define NB 2
#define CIN 64
#define TF 16
#define HF 48
#define WF 48
#define tT 8
#define tH 24
#define tW 24
#define NN 4608             // tT*tH*tW
#define HWt 576             // tH*tW
#define NFULL 36864         // TF*HF*WF
#define QSCALE 0.7213475204444817f   // 0.5 * log2(e)

// -------- scratch (device globals; no allocations) --------
__device__ float g_xr[2*NB*CIN*NN];       // [src][b][c][n]
__device__ __align__(16) __nv_bfloat16 g_qb  [NB*NN*16];
__device__ __align__(16) __nv_bfloat16 g_kb  [NB*NN*16];
__device__ __align__(16) __nv_bfloat16 g_qsab[NB*NN*16];
__device__ __align__(16) __nv_bfloat16 g_ksab[NB*NN*16];
__device__ __align__(16) __nv_bfloat16 g_vtb [NB*32*NN];   // [b][chan][key]
__device__ __align__(16) __nv_bfloat16 g_vsatb[NB*32*NN];
__device__ float g_out[2*NB*NN*32];       // [attn][b][n][c]
__device__ float g_comb[NB*64*NN];        // [b][c][n]
__device__ double g_red[8];               // [attn*2+b][{sum,sumsq}]

// ---------------- K0: zero reduction buffer ----------------
__global__ void k_zero() {
    if (threadIdx.x < 8) g_red[threadIdx.x] = 0.0;
}

// ---------------- K1: trilinear downsample ----------------
__global__ void k_resize_down(const float* __restrict__ x, const float* __restrict__ xc) {
    int idx = blockIdx.x * blockDim.x + threadIdx.x;
    const int total = 2*NB*CIN*NN;
    if (idx >= total) return;
    int n = idx % NN;
    int rest = idx / NN;
    int c = rest % CIN; rest /= CIN;
    int b = rest % NB;
    int src = rest / NB;

    int ww = n % tW;
    int hh = (n / tW) % tH;
    int tt = n / HWt;

    float pt = (float)tt * ((float)(TF-1)/(float)(tT-1));
    int t0 = (int)floorf(pt); t0 = t0 < 0 ? 0 : (t0 > TF-1 ? TF-1 : t0);
    int t1 = t0+1 > TF-1 ? TF-1 : t0+1;
    float wt = pt - (float)t0;

    float ph = (float)hh * ((float)(HF-1)/(float)(tH-1));
    int h0 = (int)floorf(ph); h0 = h0 < 0 ? 0 : (h0 > HF-1 ? HF-1 : h0);
    int h1 = h0+1 > HF-1 ? HF-1 : h0+1;
    float wh = ph - (float)h0;

    float pw = (float)ww * ((float)(WF-1)/(float)(tW-1));
    int w0 = (int)floorf(pw); w0 = w0 < 0 ? 0 : (w0 > WF-1 ? WF-1 : w0);
    int w1 = w0+1 > WF-1 ? WF-1 : w0+1;
    float wwf = pw - (float)w0;

    const float* sp = src ? xc : x;
    const float* base = sp + (size_t)(b*CIN + c) * NFULL;

    float a00 = base[t0*HF*WF + h0*WF + w0];
    float a01 = base[t0*HF*WF + h0*WF + w1];
    float a10 = base[t0*HF*WF + h1*WF + w0];
    float a11 = base[t0*HF*WF + h1*WF + w1];
    float b00 = base[t1*HF*WF + h0*WF + w0];
    float b01 = base[t1*HF*WF + h0*WF + w1];
    float b10 = base[t1*HF*WF + h1*WF + w0];
    float b11 = base[t1*HF*WF + h1*WF + w1];

    float va0 = a00 + (a01 - a00)*wwf;
    float va1 = a10 + (a11 - a10)*wwf;
    float vb0 = b00 + (b01 - b00)*wwf;
    float vb1 = b10 + (b11 - b10)*wwf;
    float va = va0 + (va1 - va0)*wh;
    float vb = vb0 + (vb1 - vb0)*wh;
    g_xr[idx] = va + (vb - va)*wt;
}

// ---------------- K2: down-proj + projections + RoPE (bf16 outputs) ----------------
__global__ void k_proj(const float* __restrict__ wd,  const float* __restrict__ bd,
                       const float* __restrict__ wdc, const float* __restrict__ bdc,
                       const float* __restrict__ wq,  const float* __restrict__ bq,
                       const float* __restrict__ wk,  const float* __restrict__ bk,
                       const float* __restrict__ wv,  const float* __restrict__ bv,
                       const float* __restrict__ wqs, const float* __restrict__ bqs,
                       const float* __restrict__ wks, const float* __restrict__ bks,
                       const float* __restrict__ wvs, const float* __restrict__ bvs,
                       const float* __restrict__ offE, const float* __restrict__ offC) {
    __shared__ float s[8192 + 192];
    float* s_wd  = s;           // 2048
    float* s_wdc = s + 2048;    // 2048
    float* s_wq  = s + 4096;    // 512
    float* s_wk  = s + 4608;    // 512
    float* s_wqs = s + 5120;    // 512
    float* s_wks = s + 5632;    // 512
    float* s_wv  = s + 6144;    // 1024
    float* s_wvs = s + 7168;    // 1024
    float* s_b   = s + 8192;    // 192 biases

    int tid = threadIdx.x;
    for (int i = tid; i < 2048; i += 64) { s_wd[i] = wd[i]; s_wdc[i] = wdc[i]; }
    for (int i = tid; i < 512;  i += 64) { s_wq[i] = wq[i]; s_wk[i] = wk[i]; s_wqs[i] = wqs[i]; s_wks[i] = wks[i]; }
    for (int i = tid; i < 1024; i += 64) { s_wv[i] = wv[i]; s_wvs[i] = wvs[i]; }
    if (tid < 32) { s_b[tid] = bd[tid];  s_b[32+tid]  = bdc[tid];
                    s_b[128+tid] = bv[tid]; s_b[160+tid] = bvs[tid]; }
    if (tid < 16) { s_b[64+tid] = bq[tid];  s_b[80+tid]  = bk[tid];
                    s_b[96+tid] = bqs[tid]; s_b[112+tid] = bks[tid]; }
    __syncthreads();

    int gid = blockIdx.x * blockDim.x + tid;
    if (gid >= NB*NN) return;
    int b = gid / NN, n = gid % NN;

    float xd[32], xcd[32];
    #pragma unroll
    for (int o = 0; o < 32; o++) { xd[o] = s_b[o]; xcd[o] = s_b[32+o]; }

    const float* xrx = g_xr + ((size_t)(0*NB + b) * CIN) * NN + n;
    const float* xrc = g_xr + ((size_t)(1*NB + b) * CIN) * NN + n;
    for (int c = 0; c < 64; c++) {
        float vx = xrx[(size_t)c * NN];
        float vc = xrc[(size_t)c * NN];
        #pragma unroll
        for (int o = 0; o < 32; o++) {
            xd[o]  += s_wd [o*64 + c] * vx;
            xcd[o] += s_wdc[o*64 + c] * vc;
        }
    }

    // RoPE factors
    int t = n / HWt;
    float se[8], ce[8], scf[8], ccf[8];
    #pragma unroll
    for (int i = 0; i < 8; i++) {
        float invf = powf(10000.0f, -(float)i / 8.0f);
        float f = (float)t * invf;
        float sv = sinf(f), cv = cosf(f);
        float oe = offE[i*500 + t];
        float oc = offC[i*500 + t];
        se[i]  = sv + oe; ce[i]  = cv + oe;
        scf[i] = sv + oc; ccf[i] = cv + oc;
    }

    float pre[16];
    // q (cross) from xd, rope sin_e/cos_e, scaled by QSCALE
    #pragma unroll
    for (int o = 0; o < 16; o++) {
        float a = s_b[64+o];
        #pragma unroll
        for (int c = 0; c < 32; c++) a += s_wq[o*32+c] * xd[c];
        pre[o] = a;
    }
    {
        __nv_bfloat16* qo = g_qb + ((size_t)b*NN + n) * 16;
        #pragma unroll
        for (int i = 0; i < 8; i++) {
            qo[i]   = __float2bfloat16((pre[i]*ce[i]   - pre[i+8]*se[i]) * QSCALE);
            qo[i+8] = __float2bfloat16((pre[i+8]*ce[i] + pre[i]*se[i]) * QSCALE);
        }
    }
    // k (cross) from xcd, rope sin_c/cos_c
    #pragma unroll
    for (int o = 0; o < 16; o++) {
        float a = s_b[80+o];
        #pragma unroll
        for (int c = 0; c < 32; c++) a += s_wk[o*32+c] * xcd[c];
        pre[o] = a;
    }
    {
        __nv_bfloat16* ko = g_kb + ((size_t)b*NN + n) * 16;
        #pragma unroll
        for (int i = 0; i < 8; i++) {
            ko[i]   = __float2bfloat16(pre[i]*ccf[i]   - pre[i+8]*scf[i]);
            ko[i+8] = __float2bfloat16(pre[i+8]*ccf[i] + pre[i]*scf[i]);
        }
    }
    // q_sa from xcd, rope sin_e/cos_e, scaled
    #pragma unroll
    for (int o = 0; o < 16; o++) {
        float a = s_b[96+o];
        #pragma unroll
        for (int c = 0; c < 32; c++) a += s_wqs[o*32+c] * xcd[c];
        pre[o] = a;
    }
    {
        __nv_bfloat16* qo = g_qsab + ((size_t)b*NN + n) * 16;
        #pragma unroll
        for (int i = 0; i < 8; i++) {
            qo[i]   = __float2bfloat16((pre[i]*ce[i]   - pre[i+8]*se[i]) * QSCALE);
            qo[i+8] = __float2bfloat16((pre[i+8]*ce[i] + pre[i]*se[i]) * QSCALE);
        }
    }
    // k_sa from xcd, rope sin_e/cos_e
    #pragma unroll
    for (int o = 0; o < 16; o++) {
        float a = s_b[112+o];
        #pragma unroll
        for (int c = 0; c < 32; c++) a += s_wks[o*32+c] * xcd[c];
        pre[o] = a;
    }
    {
        __nv_bfloat16* ko = g_ksab + ((size_t)b*NN + n) * 16;
        #pragma unroll
        for (int i = 0; i < 8; i++) {
            ko[i]   = __float2bfloat16(pre[i]*ce[i]   - pre[i+8]*se[i]);
            ko[i+8] = __float2bfloat16(pre[i+8]*ce[i] + pre[i]*se[i]);
        }
    }
    // v, v_sa — stored transposed [b][chan][key], bf16
    #pragma unroll
    for (int o = 0; o < 32; o++) {
        float a = s_b[128+o], a2 = s_b[160+o];
        #pragma unroll
        for (int c = 0; c < 32; c++) {
            a  += s_wv [o*32+c] * xcd[c];
            a2 += s_wvs[o*32+c] * xcd[c];
        }
        g_vtb  [((size_t)b*32 + o) * NN + n] = __float2bfloat16(a);
        g_vsatb[((size_t)b*32 + o) * NN + n] = __float2bfloat16(a2);
    }
}

// ---------------- K3: FlashAttention-2 with mma.sync bf16 ----------------
__device__ __forceinline__ void mma_bf16(float* d, const unsigned* a, const unsigned* b,
                                         const float* c) {
    asm volatile(
        "mma.sync.aligned.m16n8k16.row.col.f32.bf16.bf16.f32 "
        "{%0,%1,%2,%3}, {%4,%5,%6,%7}, {%8,%9}, {%10,%11,%12,%13};\n"
        : "=f"(d[0]), "=f"(d[1]), "=f"(d[2]), "=f"(d[3])
        : "r"(a[0]), "r"(a[1]), "r"(a[2]), "r"(a[3]),
          "r"(b[0]), "r"(b[1]),
          "f"(c[0]), "f"(c[1]), "f"(c[2]), "f"(c[3]));
}

__device__ __forceinline__ unsigned pack_bf2(float lo, float hi) {
    __nv_bfloat162 h = __floats2bfloat162_rn(lo, hi);   // x=lo, y=hi
    return *(unsigned*)&h;
}

#define KT 64
#define VPAD 72   // Vt smem row stride in bf16 (conflict-free)

__global__ void __launch_bounds__(128) k_attn() {
    int zz = blockIdx.y;          // a*2 + b
    int a = zz >> 1, b = zz & 1;
    const __nv_bfloat16* qb  = a ? g_qsab : g_qb;
    const __nv_bfloat16* kbp = a ? g_ksab : g_kb;
    const __nv_bfloat16* vtp = a ? g_vsatb : g_vtb;

    int warp = threadIdx.x >> 5, lane = threadIdx.x & 31;
    int g = lane >> 2, tig = lane & 3;
    int qbase = blockIdx.x * 64 + warp * 16;

    __shared__ __align__(16) __nv_bfloat16 sk[KT*16];       // [key][16]
    __shared__ __align__(16) __nv_bfloat16 sv[32*VPAD];     // [chan][key] padded
    __shared__ double sred[2*128];

    // Q fragments (held in registers for all tiles)
    unsigned qa[4];
    {
        const unsigned* q0 = (const unsigned*)(qb + ((size_t)b*NN + qbase + g) * 16);
        const unsigned* q1 = (const unsigned*)(qb + ((size_t)b*NN + qbase + g + 8) * 16);
        qa[0] = q0[tig]; qa[1] = q1[tig]; qa[2] = q0[tig+4]; qa[3] = q1[tig+4];
    }

    float o[4][4];
    #pragma unroll
    for (int c = 0; c < 4; c++)
        #pragma unroll
        for (int e = 0; e < 4; e++) o[c][e] = 0.f;
    float mlo = -INFINITY, mhi = -INFINITY, dlo = 0.f, dhi = 0.f;

    for (int kb0 = 0; kb0 < NN; kb0 += KT) {
        __syncthreads();
        // fill K tile: 64x16 bf16 = 512 words
        {
            const unsigned* src = (const unsigned*)(kbp + ((size_t)b*NN + kb0) * 16);
            unsigned* dst = (unsigned*)sk;
            #pragma unroll
            for (int i = 0; i < 4; i++) dst[threadIdx.x + 128*i] = src[threadIdx.x + 128*i];
        }
        // fill V tile transposed+padded: 32 chans x 32 words
        {
            unsigned* dst = (unsigned*)sv;
            #pragma unroll
            for (int i = 0; i < 8; i++) {
                int idx = threadIdx.x + 128*i;   // 0..1023
                int ch = idx >> 5, w = idx & 31;
                dst[ch*(VPAD/2) + w] =
                    ((const unsigned*)(vtp + ((size_t)b*32 + ch) * NN + kb0))[w];
            }
        }
        __syncthreads();

        // S = Q K^T  (8 n-tiles of 8 keys)
        float s[8][4];
        #pragma unroll
        for (int j = 0; j < 8; j++) {
            unsigned bfr[2];
            const unsigned* kr = (const unsigned*)(sk + (j*8 + g) * 16);
            bfr[0] = kr[tig]; bfr[1] = kr[tig + 4];
            float z[4] = {0.f, 0.f, 0.f, 0.f};
            mma_bf16(s[j], qa, bfr, z);
        }

        // row maxes (this tile)
        float tlo = s[0][0], thi = s[0][2];
        #pragma unroll
        for (int j = 0; j < 8; j++) {
            tlo = fmaxf(tlo, fmaxf(s[j][0], s[j][1]));
            thi = fmaxf(thi, fmaxf(s[j][2], s[j][3]));
        }
        tlo = fmaxf(tlo, __shfl_xor_sync(0xffffffffu, tlo, 1));
        tlo = fmaxf(tlo, __shfl_xor_sync(0xffffffffu, tlo, 2));
        thi = fmaxf(thi, __shfl_xor_sync(0xffffffffu, thi, 1));
        thi = fmaxf(thi, __shfl_xor_sync(0xffffffffu, thi, 2));

        float mlo_n = fmaxf(mlo, tlo);
        float mhi_n = fmaxf(mhi, thi);
        float clo = exp2f(mlo - mlo_n);
        float chi = exp2f(mhi - mhi_n);
        mlo = mlo_n; mhi = mhi_n;
        dlo *= clo; dhi *= chi;
        #pragma unroll
        for (int c = 0; c < 4; c++) {
            o[c][0] *= clo; o[c][1] *= clo;
            o[c][2] *= chi; o[c][3] *= chi;
        }

        // P = exp2(S - m), accumulate denom, PV MMAs
        #pragma unroll
        for (int s2 = 0; s2 < 4; s2++) {
            float p00 = exp2f(s[2*s2][0]   - mlo), p01 = exp2f(s[2*s2][1]   - mlo);
            float p02 = exp2f(s[2*s2][2]   - mhi), p03 = exp2f(s[2*s2][3]   - mhi);
            float p10 = exp2f(s[2*s2+1][0] - mlo), p11 = exp2f(s[2*s2+1][1] - mlo);
            float p12 = exp2f(s[2*s2+1][2] - mhi), p13 = exp2f(s[2*s2+1][3] - mhi);
            dlo += p00 + p01 + p10 + p11;
            dhi += p02 + p03 + p12 + p13;
            unsigned pa[4];
            pa[0] = pack_bf2(p00, p01);
            pa[1] = pack_bf2(p02, p03);
            pa[2] = pack_bf2(p10, p11);
            pa[3] = pack_bf2(p12, p13);
            #pragma unroll
            for (int c = 0; c < 4; c++) {
                unsigned bfr[2];
                const unsigned* vr = (const unsigned*)sv + (8*c + g) * (VPAD/2);
                bfr[0] = vr[8*s2 + tig];
                bfr[1] = vr[8*s2 + tig + 4];
                mma_bf16(o[c], pa, bfr, o[c]);
            }
        }
    }

    // quad-reduce denominators
    dlo += __shfl_xor_sync(0xffffffffu, dlo, 1);
    dlo += __shfl_xor_sync(0xffffffffu, dlo, 2);
    dhi += __shfl_xor_sync(0xffffffffu, dhi, 1);
    dhi += __shfl_xor_sync(0xffffffffu, dhi, 2);
    float ilo = 1.f / dlo, ihi = 1.f / dhi;

    // write outputs + local groupnorm sums
    float lsum = 0.f, lsum2 = 0.f;
    {
        float* rlo = g_out + ((size_t)zz*NN + qbase + g) * 32;
        float* rhi = g_out + ((size_t)zz*NN + qbase + g + 8) * 32;
        #pragma unroll
        for (int c = 0; c < 4; c++) {
            float v0 = o[c][0]*ilo, v1 = o[c][1]*ilo;
            float v2 = o[c][2]*ihi, v3 = o[c][3]*ihi;
            rlo[8*c + 2*tig]     = v0;
            rlo[8*c + 2*tig + 1] = v1;
            rhi[8*c + 2*tig]     = v2;
            rhi[8*c + 2*tig + 1] = v3;
            lsum  += v0 + v1 + v2 + v3;
            lsum2 += v0*v0 + v1*v1 + v2*v2 + v3*v3;
        }
    }

    // block-reduce stats -> atomicAdd
    __syncthreads();
    sred[threadIdx.x]       = (double)lsum;
    sred[128 + threadIdx.x] = (double)lsum2;
    __syncthreads();
    for (int st = 64; st > 0; st >>= 1) {
        if (threadIdx.x < st) {
            sred[threadIdx.x]       += sred[threadIdx.x + st];
            sred[128 + threadIdx.x] += sred[128 + threadIdx.x + st];
        }
        __syncthreads();
    }
    if (threadIdx.x == 0) {
        atomicAdd(&g_red[zz*2],     sred[0]);
        atomicAdd(&g_red[zz*2 + 1], sred[128]);
    }
}

// ---------------- K5: groupnorm + up-proj + combine ----------------
__global__ void k_comb(const float* __restrict__ gnw,  const float* __restrict__ gnb,
                       const float* __restrict__ gnws, const float* __restrict__ gnbs,
                       const float* __restrict__ wup,  const float* __restrict__ bup,
                       const float* __restrict__ wups, const float* __restrict__ bups) {
    __shared__ float s[4096 + 128 + 128 + 8];
    float* s_wup  = s;              // 2048 (64x32)
    float* s_wups = s + 2048;       // 2048
    float* s_gnw  = s + 4096;       // 32
    float* s_gnb  = s + 4128;
    float* s_gnws = s + 4160;
    float* s_gnbs = s + 4192;
    float* s_bup  = s + 4224;       // 64
    float* s_bups = s + 4288;       // 64
    float* s_st   = s + 4352;       // 8: mean/rstd per zz

    int tid = threadIdx.x;
    for (int i = tid; i < 2048; i += 256) { s_wup[i] = wup[i]; s_wups[i] = wups[i]; }
    if (tid < 32) { s_gnw[tid] = gnw[tid]; s_gnb[tid] = gnb[tid];
                    s_gnws[tid] = gnws[tid]; s_gnbs[tid] = gnbs[tid]; }
    if (tid < 64) { s_bup[tid] = bup[tid]; s_bups[tid] = bups[tid]; }
    if (tid < 4) {
        const double M = (double)NN * 32.0;
        double mean = g_red[tid*2] / M;
        double var  = g_red[tid*2 + 1] / M - mean * mean;
        s_st[tid*2]     = (float)mean;
        s_st[tid*2 + 1] = (float)(1.0 / sqrt(var + 1e-5));
    }
    __syncthreads();

    int idx = blockIdx.x * blockDim.x + tid;
    if (idx >= NB*64*NN) return;
    int n = idx % NN;
    int rest = idx / NN;
    int o = rest % 64;
    int b = rest / 64;

    const float* p0 = g_out + ((size_t)(0*2 + b)*NN + n) * 32;  // cross (zz = b)
    const float* p1 = g_out + ((size_t)(2 + b)*NN + n) * 32;    // self  (zz = 2+b)
    float mu0 = s_st[b*2],       rs0 = s_st[b*2 + 1];
    float mu1 = s_st[4 + b*2],   rs1 = s_st[4 + b*2 + 1];

    float a0 = s_bup[o], a1 = s_bups[o];
    #pragma unroll
    for (int c = 0; c < 32; c++) {
        float xn0 = (p0[c] - mu0) * rs0 * s_gnw[c]  + s_gnb[c];
        float xn1 = (p1[c] - mu1) * rs1 * s_gnws[c] + s_gnbs[c];
        a0 += s_wup[o*32 + c]  * xn0;
        a1 += s_wups[o*32 + c] * xn1;
    }
    g_comb[((size_t)b*64 + o) * NN + n] = a1 - 0.5f * a0;
}

// ---------------- K6: trilinear upsample + residual ----------------
__global__ void k_final(const float* __restrict__ xc, float* __restrict__ out) {
    int idx = blockIdx.x * blockDim.x + threadIdx.x;
    const int total = NB*64*NFULL;
    if (idx >= total) return;
    int w = idx % WF;
    int rest = idx / WF;
    int h = rest % HF; rest /= HF;
    int t = rest % TF; rest /= TF;
    int c = rest % 64;
    int b = rest / 64;

    float pt = (float)t * ((float)(tT-1)/(float)(TF-1));
    int t0 = (int)floorf(pt); t0 = t0 < 0 ? 0 : (t0 > tT-1 ? tT-1 : t0);
    int t1 = t0+1 > tT-1 ? tT-1 : t0+1;
    float wt = pt - (float)t0;

    float ph = (float)h * ((float)(tH-1)/(float)(HF-1));
    int h0 = (int)floorf(ph); h0 = h0 < 0 ? 0 : (h0 > tH-1 ? tH-1 : h0);
    int h1 = h0+1 > tH-1 ? tH-1 : h0+1;
    float wh = ph - (float)h0;

    float pw = (float)w * ((float)(tW-1)/(float)(WF-1));
    int w0 = (int)floorf(pw); w0 = w0 < 0 ? 0 : (w0 > tW-1 ? tW-1 : w0);
    int w1 = w0+1 > tW-1 ? tW-1 : w0+1;
    float wwf = pw - (float)w0;

    const float* base = g_comb + ((size_t)b*64 + c) * NN;
    float a00 = base[t0*HWt + h0*tW + w0];
    float a01 = base[t0*HWt + h0*tW + w1];
    float a10 = base[t0*HWt + h1*tW + w0];
    float a11 = base[t0*HWt + h1*tW + w1];
    float b00 = base[t1*HWt + h0*tW + w0];
    float b01 = base[t1*HWt + h0*tW + w1];
    float b10 = base[t1*HWt + h1*tW + w0];
    float b11 = base[t1*HWt + h1*tW + w1];

    float va0 = a00 + (a01 - a00)*wwf;
    float va1 = a10 + (a11 - a10)*wwf;
    float vb0 = b00 + (b01 - b00)*wwf;
    float vb1 = b10 + (b11 - b10)*wwf;
    float va = va0 + (va1 - va0)*wh;
    float vb = vb0 + (vb1 - vb0)*wh;
    float v = va + (vb - va)*wt;

    out[idx] = v + xc[idx];
}

// ---------------- launch ----------------
extern "C" void kernel_launch(void* const* d_in, const int* in_sizes, int n_in,
                              void* d_out, int out_size) {
    const float* x    = (const float*)d_in[0];
    const float* xc   = (const float*)d_in[1];
    const float* wd   = (const float*)d_in[2];
    const float* bd   = (const float*)d_in[3];
    const float* wdc  = (const float*)d_in[4];
    const float* bdc  = (const float*)d_in[5];
    const float* wq   = (const float*)d_in[6];
    const float* bq   = (const float*)d_in[7];
    const float* wk   = (const float*)d_in[8];
    const float* bk   = (const float*)d_in[9];
    const float* wv   = (const float*)d_in[10];
    const float* bv   = (const float*)d_in[11];
    const float* wqs  = (const float*)d_in[12];
    const float* bqs  = (const float*)d_in[13];
    const float* wks  = (const float*)d_in[14];
    const float* bks  = (const float*)d_in[15];
    const float* wvs  = (const float*)d_in[16];
    const float* bvs  = (const float*)d_in[17];
    const float* gnw  = (const float*)d_in[18];
    const float* gnb  = (const float*)d_in[19];
    const float* gnws = (const float*)d_in[20];
    const float* gnbs = (const float*)d_in[21];
    const float* wup  = (const float*)d_in[22];
    const float* bup  = (const float*)d_in[23];
    const float* wups = (const float*)d_in[24];
    const float* bups = (const float*)d_in[25];
    const float* offE = (const float*)d_in[26];
    const float* offC = (const float*)d_in[27];
    float* out = (float*)d_out;

    k_zero<<<1, 32>>>();
    k_resize_down<<<(2*NB*CIN*NN + 255)/256, 256>>>(x, xc);
    k_proj<<<(NB*NN + 63)/64, 64>>>(wd, bd, wdc, bdc, wq, bq, wk, bk, wv, bv,
                                    wqs, bqs, wks, bks, wvs, bvs, offE, offC);
    dim3 ag(NN/64, 4, 1);
    k_attn<<<ag, 128>>>();
    k_comb<<<(NB*64*NN + 255)/256, 256>>>(gnw, gnb, gnws, gnbs, wup, bup, wups, bups);
    k_final<<<(NB*64*NFULL + 255)/256, 256>>>(xc, out);
}